// round 2
// baseline (speedup 1.0000x reference)
#include <cuda_runtime.h>

// out = segment_sum(x, batch) ; batch sorted, N=1e6 rows, C=128 channels,
// G=10000 segments. softmax over a size-1 axis == 1.0 -> W/b are dead inputs.
// NOTE: JAX without x64 downcasts int64 -> int32, so batch is int32 on device.

#define C 128
#define ROWS_PER_BLOCK 512

__global__ void zero_out_kernel(float4* __restrict__ out, int n4) {
    int i = blockIdx.x * blockDim.x + threadIdx.x;
    if (i < n4) out[i] = make_float4(0.f, 0.f, 0.f, 0.f);
}

__global__ __launch_bounds__(C) void seg_sum_kernel(
    const float* __restrict__ x,
    const int* __restrict__ batch,
    float* __restrict__ out,
    int n)
{
    const int c = threadIdx.x;                 // channel owned by this thread
    int row0 = blockIdx.x * ROWS_PER_BLOCK;
    int row1 = min(row0 + ROWS_PER_BLOCK, n);
    if (row0 >= row1) return;

    int cur = __ldg(&batch[row0]);
    float acc = 0.f;

    #pragma unroll 4
    for (int r = row0; r < row1; ++r) {
        // batch[r] is uniform across the block -> convergent branch
        int b = __ldg(&batch[r]);
        float v = __ldg(&x[(size_t)r * C + c]);
        if (b != cur) {
            atomicAdd(&out[(size_t)cur * C + c], acc);  // REDG, no return trip
            acc = 0.f;
            cur = b;
        }
        acc += v;
    }
    atomicAdd(&out[(size_t)cur * C + c], acc);
}

extern "C" void kernel_launch(void* const* d_in, const int* in_sizes, int n_in,
                              void* d_out, int out_size)
{
    const float* x     = (const float*)d_in[0];
    const int*   batch = (const int*)d_in[1];
    // d_in[2] = W, d_in[3] = b : mathematically dead (softmax over size-1 axis)
    float* out = (float*)d_out;

    const int n = in_sizes[0] / C;    // rows of x (robust to batch dtype width)

    // 1) zero the (poisoned) output
    int n4 = out_size / 4;            // out_size = G*C, divisible by 4
    zero_out_kernel<<<(n4 + 255) / 256, 256>>>((float4*)out, n4);

    // 2) streaming segmented sum: one thread per channel, 512 rows per block
    int blocks = (n + ROWS_PER_BLOCK - 1) / ROWS_PER_BLOCK;
    seg_sum_kernel<<<blocks, C>>>(x, batch, out, n);
}

// round 3
// speedup vs baseline: 1.1682x; 1.1682x over previous
#include <cuda_runtime.h>

// out = segment_sum(x, batch); batch sorted int32, N=1e6 rows, C=128, G=10000.
// softmax over size-1 axis == 1.0 -> W/b dead.
// R3: float4 path. One warp = one row (32 lanes x 4 channels). 4 warps/block
// process 4 rows per iteration; unroll 4 for MLP.

#define C 128
#define C4 (C / 4)              // 32 float4 per row
#define WARPS 4
#define ROWS_PER_BLOCK 512

__global__ void zero_out_kernel(float4* __restrict__ out, int n4) {
    int i = blockIdx.x * blockDim.x + threadIdx.x;
    if (i < n4) out[i] = make_float4(0.f, 0.f, 0.f, 0.f);
}

__global__ __launch_bounds__(WARPS * 32) void seg_sum_kernel(
    const float4* __restrict__ x4,
    const int* __restrict__ batch,
    float* __restrict__ out,
    int n)
{
    const int warp = threadIdx.x >> 5;
    const int lane = threadIdx.x & 31;          // owns channels [4*lane, 4*lane+4)

    int blk0 = blockIdx.x * ROWS_PER_BLOCK;
    int blk1 = min(blk0 + ROWS_PER_BLOCK, n);
    int row0 = blk0 + warp;                      // this warp visits row0, row0+4, ...
    if (row0 >= blk1) return;

    int cur = __ldg(&batch[row0]);
    float4 acc = make_float4(0.f, 0.f, 0.f, 0.f);

    #pragma unroll 4
    for (int r = row0; r < blk1; r += WARPS) {
        int b = __ldg(&batch[r]);                // uniform in warp -> broadcast
        float4 v = __ldg(&x4[(size_t)r * C4 + lane]);
        if (b != cur) {                          // warp-convergent, rare
            float* o = &out[(size_t)cur * C + 4 * lane];
            atomicAdd(o + 0, acc.x);
            atomicAdd(o + 1, acc.y);
            atomicAdd(o + 2, acc.z);
            atomicAdd(o + 3, acc.w);
            acc = make_float4(0.f, 0.f, 0.f, 0.f);
            cur = b;
        }
        acc.x += v.x; acc.y += v.y; acc.z += v.z; acc.w += v.w;
    }
    float* o = &out[(size_t)cur * C + 4 * lane];
    atomicAdd(o + 0, acc.x);
    atomicAdd(o + 1, acc.y);
    atomicAdd(o + 2, acc.z);
    atomicAdd(o + 3, acc.w);
}

extern "C" void kernel_launch(void* const* d_in, const int* in_sizes, int n_in,
                              void* d_out, int out_size)
{
    const float4* x4    = (const float4*)d_in[0];
    const int*    batch = (const int*)d_in[1];
    // d_in[2] = W, d_in[3] = b : dead (softmax over size-1 axis)
    float* out = (float*)d_out;

    const int n = in_sizes[0] / C;               // rows of x

    int n4 = out_size / 4;
    zero_out_kernel<<<(n4 + 255) / 256, 256>>>((float4*)out, n4);

    int blocks = (n + ROWS_PER_BLOCK - 1) / ROWS_PER_BLOCK;
    seg_sum_kernel<<<blocks, WARPS * 32>>>(x4, batch, out, n);
}

// round 4
// speedup vs baseline: 1.2182x; 1.0428x over previous
#include <cuda_runtime.h>

// out = segment_sum(x, batch); batch sorted int32, N=1e6, C=128, G=10000.
// softmax over size-1 axis == 1.0 -> W/b dead inputs.
// R4: block-per-segment. Precompute segment start offsets from the sorted
// batch array, then each block streams its contiguous row range with pure
// LDG.128 + FADD (no per-row index loads, no branches, no atomics), smem-
// reduces across warps, and stores its output row directly (no zero pass).

#define C 128
#define C4 (C / 4)
#define WARPS 4
#define MAX_SEG 10000

__device__ int g_start[MAX_SEG + 1];   // start[g] = first row with batch[i] >= g

// Boundary scatter: start[g] for every g in (batch[i-1], batch[i]] is i.
__global__ void offsets_kernel(const int* __restrict__ batch, int n, int nseg) {
    int i = blockIdx.x * blockDim.x + threadIdx.x;
    if (i >= n) return;
    int b1 = __ldg(&batch[i]);
    int b0 = (i == 0) ? -1 : __ldg(&batch[i - 1]);
    for (int g = b0 + 1; g <= b1; ++g) g_start[g] = i;       // rare, ~G total
    if (i == n - 1)
        for (int g = b1 + 1; g <= nseg; ++g) g_start[g] = n; // trailing empties
}

__global__ __launch_bounds__(WARPS * 32) void seg_sum_kernel(
    const float4* __restrict__ x4,
    float4* __restrict__ out4)
{
    const int g    = blockIdx.x;
    const int warp = threadIdx.x >> 5;
    const int lane = threadIdx.x & 31;       // owns channels [4*lane, 4*lane+4)

    const int s = g_start[g];
    const int e = g_start[g + 1];

    float4 acc = make_float4(0.f, 0.f, 0.f, 0.f);
    #pragma unroll 4
    for (int r = s + warp; r < e; r += WARPS) {
        float4 v = __ldg(&x4[(size_t)r * C4 + lane]);
        acc.x += v.x; acc.y += v.y; acc.z += v.z; acc.w += v.w;
    }

    __shared__ float4 sacc[WARPS][C4];
    sacc[warp][lane] = acc;
    __syncthreads();

    if (warp == 0) {
        float4 a = sacc[0][lane], b = sacc[1][lane],
               c = sacc[2][lane], d = sacc[3][lane];
        a.x += b.x + c.x + d.x;
        a.y += b.y + c.y + d.y;
        a.z += b.z + c.z + d.z;
        a.w += b.w + c.w + d.w;
        out4[(size_t)g * C4 + lane] = a;     // direct store; zeros if empty seg
    }
}

extern "C" void kernel_launch(void* const* d_in, const int* in_sizes, int n_in,
                              void* d_out, int out_size)
{
    const float4* x4    = (const float4*)d_in[0];
    const int*    batch = (const int*)d_in[1];
    // d_in[2] = W, d_in[3] = b : dead (softmax over size-1 axis)
    float4* out4 = (float4*)d_out;

    const int n    = in_sizes[0] / C;        // rows of x
    const int nseg = out_size / C;           // number of segments (10000)

    offsets_kernel<<<(n + 255) / 256, 256>>>(batch, n, nseg);
    seg_sum_kernel<<<nseg, WARPS * 32>>>(x4, out4);
}